// round 1
// baseline (speedup 1.0000x reference)
#include <cuda_runtime.h>
#include <cstddef>

typedef unsigned long long ULL;

#define EPSF 1e-5f
#define NB 8
#define HW 256
#define NODES 340      // 4 views * 5 T * 17 V
#define CIN0 18

// ---- packed-f32x2 helpers (Blackwell) ----
__device__ __forceinline__ ULL f2fma(ULL a, ULL b, ULL c){
  ULL d; asm("fma.rn.f32x2 %0,%1,%2,%3;" : "=l"(d) : "l"(a), "l"(b), "l"(c)); return d;
}
__device__ __forceinline__ ULL pkdup(float a){
  ULL d; asm("mov.b64 %0,{%1,%1};" : "=l"(d) : "f"(a)); return d;
}
__device__ __forceinline__ ULL pk(float a, float b){
  ULL d; asm("mov.b64 %0,{%1,%2};" : "=l"(d) : "f"(a), "f"(b)); return d;
}
__device__ __forceinline__ float2 up2(ULL a){
  float2 v; asm("mov.b64 {%0,%1},%2;" : "=f"(v.x), "=f"(v.y) : "l"(a)); return v;
}
__device__ __forceinline__ ULL lds2(const float* p){ return *reinterpret_cast<const ULL*>(p); }

// ---- parameter table layout (floats) ----
#define P_ASP 0          // 4*17*17 = 1156
#define P_ATM 1156       // 2*5*5 = 50
#define P_AVW 1206       // 4*4 = 16
#define P_WG0 1222       // 7*18*16 = 2016   [k][c][o]
#define P_WG1 3238       // 7*16*16 = 1792
#define P_WG2 5030       // 1792
#define P_BG  6822       // 3*7*16 = 336
#define P_S1  7158       // 336  (bn1g * rsqrt(1+eps))
#define P_B1  7494       // 336
#define P_WT  7830       // 3*7*16*16 = 5376 [l][k][c][o]
#define P_S2  13206      // 336  (bn2g * rsqrt(1+eps))
#define P_CI  13542      // 3*16 (sum_k bt*s2 + b2)
#define P_TOT 13590
#define P_PAD 13592

#define S_CUR P_PAD                 // 340*18
#define S_Y   (P_PAD + 6120)        // 340*18
#define SM_FLOATS (P_PAD + 6120 + 6120)
#define SM_BYTES (SM_FLOATS * 4)

__device__ float gP[P_TOT];

// ---------------- prep: fold BN, transpose weights, stage A matrices ----------------
__global__ void prep_kernel(const float* __restrict__ A_sp, const float* __restrict__ A_tm,
                            const float* __restrict__ A_vw,
                            const float* __restrict__ Wg0, const float* __restrict__ bg0,
                            const float* __restrict__ Wg,  const float* __restrict__ bg,
                            const float* __restrict__ bn1g, const float* __restrict__ bn1b,
                            const float* __restrict__ Wt,  const float* __restrict__ bt,
                            const float* __restrict__ bn2g, const float* __restrict__ bn2b)
{
  const int t = threadIdx.x;
  const float inv = rsqrtf(1.f + EPSF);
  for (int i = t; i < 1156; i += 256) gP[P_ASP + i] = A_sp[i];
  for (int i = t; i < 50;   i += 256) gP[P_ATM + i] = A_tm[i];
  for (int i = t; i < 16;   i += 256) gP[P_AVW + i] = A_vw[i];
  // Wg0: (7,16,18) [k][o][c] -> [k][c][o]
  for (int i = t; i < 7*16*18; i += 256){
    int k = i / 288, r = i % 288, o = r / 18, c = r % 18;
    gP[P_WG0 + (k*18 + c)*16 + o] = Wg0[i];
  }
  // Wg: (2,7,16,16) -> per-layer [k][c][o]
  for (int i = t; i < 2*7*256; i += 256){
    int l = i / 1792, r = i % 1792, k = r / 256, q = r % 256, o = q / 16, c = q % 16;
    gP[P_WG1 + l*1792 + (k*16 + c)*16 + o] = Wg[i];
  }
  for (int i = t; i < 112; i += 256) gP[P_BG + i] = bg0[i];
  for (int i = t; i < 224; i += 256) gP[P_BG + 112 + i] = bg[i];
  for (int i = t; i < 336; i += 256){
    gP[P_S1 + i] = bn1g[i] * inv;
    gP[P_B1 + i] = bn1b[i];
    gP[P_S2 + i] = bn2g[i] * inv;
  }
  // Wt: (3,7,16,16) [b][o][c] -> [b][c][o]
  for (int i = t; i < 3*7*256; i += 256){
    int b = i / 256, q = i % 256, o = q / 16, c = q % 16;
    gP[P_WT + b*256 + c*16 + o] = Wt[i];
  }
  // CINIT[l][o] = sum_k ( bt*s2 + b2 )
  for (int i = t; i < 48; i += 256){
    int l = i / 16, o = i % 16;
    float s = 0.f;
    for (int k = 0; k < 7; k++){
      int id = (l*7 + k)*16 + o;
      s += bt[id] * (bn2g[id] * inv) + bn2b[id];
    }
    gP[P_CI + i] = s;
  }
}

// ---------------- fused 3-layer ST-GCN: one CTA per (n, hw) ----------------
__global__ __launch_bounds__(192, 2)
void stgcn_kernel(const float* __restrict__ x, float* __restrict__ out)
{
  extern __shared__ float smf[];
  float* sP   = smf;
  float* sCur = smf + S_CUR;   // 340 rows x stride 18
  float* sY   = smf + S_Y;     // 340 rows x stride 18 (16 used)

  const int hw  = blockIdx.x;
  const int n   = blockIdx.y;
  const int tid = threadIdx.x;

  for (int i = tid; i < P_TOT; i += 192) sP[i] = gP[i];
  {
    const float* xb = x + ((size_t)n * NODES * CIN0) * HW + hw;
    for (int i = tid; i < NODES * CIN0; i += 192) sCur[i] = xb[(size_t)i * HW];
  }
  __syncthreads();

  const bool act  = tid < 180;
  const int  g    = tid / 9;     // g = vw*5 + tt   (0..19)
  const int  j    = tid % 9;     // v-pair slot
  const int  vw   = g / 5, tt = g % 5;
  const bool has2 = (j < 8);
  const int  v0   = 2 * j;               // j==8 -> v0 = 16
  const int  v1   = has2 ? (2*j + 1) : v0;
  const int  nd0  = g*17 + v0, nd1 = g*17 + v1;

  ULL acc0[8], acc1[8];
  float xr0[18], xr1[18];

  for (int L = 0; L < 3; ++L){
    const int Cin = L ? 16 : 18;
    const float* WgL = sP + (L == 0 ? P_WG0 : (L == 1 ? P_WG1 : P_WG2));
    const float* WtL = sP + P_WT + L*1792;
    const float* BgL = sP + P_BG + L*112;
    const float* S1L = sP + P_S1 + L*112;
    const float* B1L = sP + P_B1 + L*112;
    const float* S2L = sP + P_S2 + L*112;
    const float* CIL = sP + P_CI + L*16;

    if (act){
      for (int c = 0; c < Cin; c++){ xr0[c] = sCur[nd0*18 + c]; xr1[c] = sCur[nd1*18 + c]; }
      if (L == 0){
        #pragma unroll
        for (int op = 0; op < 8; op++){ ULL ci = lds2(CIL + 2*op); acc0[op] = ci; acc1[op] = ci; }
      } else {
        // residual appears in each of the 7 branches -> 7*x, folded into init
        #pragma unroll
        for (int op = 0; op < 8; op++){
          float a = CIL[2*op], b = CIL[2*op + 1];
          acc0[op] = pk(fmaf(7.f, xr0[2*op], a), fmaf(7.f, xr0[2*op+1], b));
          acc1[op] = pk(fmaf(7.f, xr1[2*op], a), fmaf(7.f, xr1[2*op+1], b));
        }
      }
    }

    for (int k = 0; k < 7; ++k){
      // ---- phase A: conv1 (Wg) + bg -> sY ----
      if (act){
        ULL y0[8], y1[8];
        const float* Bg = BgL + k*16;
        #pragma unroll
        for (int op = 0; op < 8; op++){ ULL b = lds2(Bg + 2*op); y0[op] = b; y1[op] = b; }
        const float* W = WgL + k*Cin*16;
        for (int c = 0; c < Cin; c++){
          ULL xa = pkdup(xr0[c]), xb = pkdup(xr1[c]);
          #pragma unroll
          for (int op = 0; op < 8; op++){
            ULL wp = lds2(W + c*16 + 2*op);
            y0[op] = f2fma(wp, xa, y0[op]);
            y1[op] = f2fma(wp, xb, y1[op]);
          }
        }
        ULL* d0 = reinterpret_cast<ULL*>(sY + nd0*18);
        #pragma unroll
        for (int op = 0; op < 8; op++) d0[op] = y0[op];
        if (has2){
          ULL* d1 = reinterpret_cast<ULL*>(sY + nd1*18);
          #pragma unroll
          for (int op = 0; op < 8; op++) d1[op] = y1[op];
        }
      }
      __syncthreads();

      // ---- phase B: adjacency agg + BN1/ReLU + conv2 (Wt) + BN2 -> acc ----
      if (act){
        ULL ag0[8], ag1[8];
        #pragma unroll
        for (int op = 0; op < 8; op++){ ag0[op] = 0ULL; ag1[op] = 0ULL; }

        if (k < 4){                       // spatial: mix over V, neighbor rows shared by the pair
          const float* A = sP + P_ASP + k*289;
          for (int i = 0; i < 17; i++){
            ULL a0 = pkdup(A[v0*17 + i]);
            ULL a1 = pkdup(A[v1*17 + i]);
            const ULL* yr = reinterpret_cast<const ULL*>(sY + (g*17 + i)*18);
            #pragma unroll
            for (int op = 0; op < 8; op++){
              ULL yv = yr[op];
              ag0[op] = f2fma(yv, a0, ag0[op]);
              ag1[op] = f2fma(yv, a1, ag1[op]);
            }
          }
        } else if (k < 6){                // temporal: mix over T
          const float* A = sP + P_ATM + (k - 4)*25 + tt*5;
          for (int tp = 0; tp < 5; tp++){
            ULL ap = pkdup(A[tp]);
            const ULL* y0r = reinterpret_cast<const ULL*>(sY + ((vw*5 + tp)*17 + v0)*18);
            const ULL* y1r = reinterpret_cast<const ULL*>(sY + ((vw*5 + tp)*17 + v1)*18);
            #pragma unroll
            for (int op = 0; op < 8; op++){
              ag0[op] = f2fma(y0r[op], ap, ag0[op]);
              ag1[op] = f2fma(y1r[op], ap, ag1[op]);
            }
          }
        } else {                          // views: mix over VIEWS
          const float* A = sP + P_AVW + vw*4;
          for (int wq = 0; wq < 4; wq++){
            ULL ap = pkdup(A[wq]);
            const ULL* y0r = reinterpret_cast<const ULL*>(sY + ((wq*5 + tt)*17 + v0)*18);
            const ULL* y1r = reinterpret_cast<const ULL*>(sY + ((wq*5 + tt)*17 + v1)*18);
            #pragma unroll
            for (int op = 0; op < 8; op++){
              ag0[op] = f2fma(y0r[op], ap, ag0[op]);
              ag1[op] = f2fma(y1r[op], ap, ag1[op]);
            }
          }
        }

        // BN1 + ReLU
        float r0[16], r1[16];
        const float* S1 = S1L + k*16; const float* B1 = B1L + k*16;
        #pragma unroll
        for (int op = 0; op < 8; op++){
          ULL s = lds2(S1 + 2*op), b = lds2(B1 + 2*op);
          float2 t0 = up2(f2fma(ag0[op], s, b));
          r0[2*op] = fmaxf(t0.x, 0.f); r0[2*op+1] = fmaxf(t0.y, 0.f);
          float2 t1 = up2(f2fma(ag1[op], s, b));
          r1[2*op] = fmaxf(t1.x, 0.f); r1[2*op+1] = fmaxf(t1.y, 0.f);
        }

        // conv2 (bias bt & b2 pre-folded into CINIT via s2)
        ULL z0[8], z1[8];
        #pragma unroll
        for (int op = 0; op < 8; op++){ z0[op] = 0ULL; z1[op] = 0ULL; }
        const float* W2 = WtL + k*256;
        for (int c = 0; c < 16; c++){
          ULL xa = pkdup(r0[c]), xb = pkdup(r1[c]);
          #pragma unroll
          for (int op = 0; op < 8; op++){
            ULL wp = lds2(W2 + c*16 + 2*op);
            z0[op] = f2fma(wp, xa, z0[op]);
            z1[op] = f2fma(wp, xb, z1[op]);
          }
        }
        const float* S2 = S2L + k*16;
        #pragma unroll
        for (int op = 0; op < 8; op++){
          ULL s = lds2(S2 + 2*op);
          acc0[op] = f2fma(z0[op], s, acc0[op]);
          acc1[op] = f2fma(z1[op], s, acc1[op]);
        }
      }
      __syncthreads();
    }

    if (L < 2){
      if (act){
        #pragma unroll
        for (int op = 0; op < 8; op++){
          float2 a = up2(acc0[op]);
          sCur[nd0*18 + 2*op]     = fmaxf(a.x, 0.f);
          sCur[nd0*18 + 2*op + 1] = fmaxf(a.y, 0.f);
          if (has2){
            float2 b = up2(acc1[op]);
            sCur[nd1*18 + 2*op]     = fmaxf(b.x, 0.f);
            sCur[nd1*18 + 2*op + 1] = fmaxf(b.y, 0.f);
          }
        }
      }
      __syncthreads();
    } else {
      if (act){
        float* o0 = out + ((size_t)(n*NODES + nd0) * 16) * HW + hw;
        #pragma unroll
        for (int op = 0; op < 8; op++){
          float2 a = up2(acc0[op]);
          o0[(size_t)(2*op)     * HW] = fmaxf(a.x, 0.f);
          o0[(size_t)(2*op + 1) * HW] = fmaxf(a.y, 0.f);
        }
        if (has2){
          float* o1 = out + ((size_t)(n*NODES + nd1) * 16) * HW + hw;
          #pragma unroll
          for (int op = 0; op < 8; op++){
            float2 b = up2(acc1[op]);
            o1[(size_t)(2*op)     * HW] = fmaxf(b.x, 0.f);
            o1[(size_t)(2*op + 1) * HW] = fmaxf(b.y, 0.f);
          }
        }
      }
    }
  }
}

extern "C" void kernel_launch(void* const* d_in, const int* in_sizes, int n_in,
                              void* d_out, int out_size)
{
  (void)in_sizes; (void)n_in; (void)out_size;
  const float* x    = (const float*)d_in[0];
  const float* A_sp = (const float*)d_in[1];
  const float* A_tm = (const float*)d_in[2];
  const float* A_vw = (const float*)d_in[3];
  const float* Wg0  = (const float*)d_in[4];
  const float* bg0  = (const float*)d_in[5];
  const float* Wg   = (const float*)d_in[6];
  const float* bg   = (const float*)d_in[7];
  const float* bn1g = (const float*)d_in[8];
  const float* bn1b = (const float*)d_in[9];
  const float* Wt   = (const float*)d_in[10];
  const float* bt   = (const float*)d_in[11];
  const float* bn2g = (const float*)d_in[12];
  const float* bn2b = (const float*)d_in[13];

  cudaFuncSetAttribute(stgcn_kernel, cudaFuncAttributeMaxDynamicSharedMemorySize, SM_BYTES);

  prep_kernel<<<1, 256>>>(A_sp, A_tm, A_vw, Wg0, bg0, Wg, bg,
                          bn1g, bn1b, Wt, bt, bn2g, bn2b);
  stgcn_kernel<<<dim3(HW, NB), 192, SM_BYTES>>>(x, (float*)d_out);
}